// round 1
// baseline (speedup 1.0000x reference)
#include <cuda_runtime.h>
#include <math.h>

// Problem dims (fixed): B=4, S=4096, DM=1024, H=16, HD=64
#define MDIM 16384   // B*S tokens
#define NDIM 1024
#define KDIM 1024

// Scratch (device globals — no allocation allowed in kernel_launch)
__device__ float g_QKV[3ull * MDIM * NDIM];   // [Q | K | V], each [MDIM, NDIM]
__device__ float g_attn[(size_t)MDIM * NDIM]; // attention output before fc

// ---------------------------------------------------------------------------
// TN GEMM tile: C[m,n] = sum_k A[m,k] * B[n,k]
// A: [MDIM, KDIM] row-major, B: [NDIM, KDIM] row-major (nn.Linear weight)
// 128x128 block tile, BK=16, 256 threads, 8x8 per thread, double-buffered smem
// ---------------------------------------------------------------------------
__device__ __forceinline__ void gemm_tn_128x128(
    const float* __restrict__ A,
    const float* __restrict__ B,
    float* __restrict__ C)
{
    const int BM = 128, BN = 128, BK = 16;
    __shared__ float As[2][BK][BM];
    __shared__ float Bs[2][BK][BN];

    const int tid = threadIdx.x;
    const int tx = tid & 15;   // n-tile coordinate (0..15)
    const int ty = tid >> 4;   // m-tile coordinate (0..15)

    const int mBase = blockIdx.y * BM;
    const int nBase = blockIdx.x * BN;

    // global tile load mapping: 256 threads load 128x16 floats (2 float4 each per operand)
    const int lRow = tid >> 2;          // 0..63
    const int lCol = (tid & 3) << 2;    // 0,4,8,12

    const float* Ap = A + (size_t)(mBase + lRow) * KDIM + lCol;
    const float* Bp = B + (size_t)(nBase + lRow) * KDIM + lCol;

    float4 ar0 = *(const float4*)(Ap);
    float4 ar1 = *(const float4*)(Ap + (size_t)64 * KDIM);
    float4 br0 = *(const float4*)(Bp);
    float4 br1 = *(const float4*)(Bp + (size_t)64 * KDIM);

    int stage = 0;
    As[0][lCol + 0][lRow] = ar0.x;
    As[0][lCol + 1][lRow] = ar0.y;
    As[0][lCol + 2][lRow] = ar0.z;
    As[0][lCol + 3][lRow] = ar0.w;
    As[0][lCol + 0][lRow + 64] = ar1.x;
    As[0][lCol + 1][lRow + 64] = ar1.y;
    As[0][lCol + 2][lRow + 64] = ar1.z;
    As[0][lCol + 3][lRow + 64] = ar1.w;
    Bs[0][lCol + 0][lRow] = br0.x;
    Bs[0][lCol + 1][lRow] = br0.y;
    Bs[0][lCol + 2][lRow] = br0.z;
    Bs[0][lCol + 3][lRow] = br0.w;
    Bs[0][lCol + 0][lRow + 64] = br1.x;
    Bs[0][lCol + 1][lRow + 64] = br1.y;
    Bs[0][lCol + 2][lRow + 64] = br1.z;
    Bs[0][lCol + 3][lRow + 64] = br1.w;
    __syncthreads();

    float acc[8][8];
#pragma unroll
    for (int i = 0; i < 8; i++)
#pragma unroll
        for (int j = 0; j < 8; j++) acc[i][j] = 0.0f;

    for (int kt = BK; kt <= KDIM; kt += BK) {
        const bool has_next = (kt < KDIM);
        if (has_next) {
            ar0 = *(const float4*)(Ap + kt);
            ar1 = *(const float4*)(Ap + kt + (size_t)64 * KDIM);
            br0 = *(const float4*)(Bp + kt);
            br1 = *(const float4*)(Bp + kt + (size_t)64 * KDIM);
        }
#pragma unroll
        for (int kk = 0; kk < BK; kk++) {
            float4 a0 = *(const float4*)(&As[stage][kk][ty * 4]);
            float4 a1 = *(const float4*)(&As[stage][kk][64 + ty * 4]);
            float4 b0 = *(const float4*)(&Bs[stage][kk][tx * 4]);
            float4 b1 = *(const float4*)(&Bs[stage][kk][64 + tx * 4]);
            float a[8] = {a0.x, a0.y, a0.z, a0.w, a1.x, a1.y, a1.z, a1.w};
            float b[8] = {b0.x, b0.y, b0.z, b0.w, b1.x, b1.y, b1.z, b1.w};
#pragma unroll
            for (int i = 0; i < 8; i++)
#pragma unroll
                for (int j = 0; j < 8; j++)
                    acc[i][j] = fmaf(a[i], b[j], acc[i][j]);
        }
        if (has_next) {
            stage ^= 1;
            As[stage][lCol + 0][lRow] = ar0.x;
            As[stage][lCol + 1][lRow] = ar0.y;
            As[stage][lCol + 2][lRow] = ar0.z;
            As[stage][lCol + 3][lRow] = ar0.w;
            As[stage][lCol + 0][lRow + 64] = ar1.x;
            As[stage][lCol + 1][lRow + 64] = ar1.y;
            As[stage][lCol + 2][lRow + 64] = ar1.z;
            As[stage][lCol + 3][lRow + 64] = ar1.w;
            Bs[stage][lCol + 0][lRow] = br0.x;
            Bs[stage][lCol + 1][lRow] = br0.y;
            Bs[stage][lCol + 2][lRow] = br0.z;
            Bs[stage][lCol + 3][lRow] = br0.w;
            Bs[stage][lCol + 0][lRow + 64] = br1.x;
            Bs[stage][lCol + 1][lRow + 64] = br1.y;
            Bs[stage][lCol + 2][lRow + 64] = br1.z;
            Bs[stage][lCol + 3][lRow + 64] = br1.w;
            __syncthreads();
        }
    }

#pragma unroll
    for (int i = 0; i < 8; i++) {
        const int m = mBase + ((i < 4) ? (ty * 4 + i) : (64 + ty * 4 + (i - 4)));
        float* cp = C + (size_t)m * NDIM + nBase;
        float4 c0 = make_float4(acc[i][0], acc[i][1], acc[i][2], acc[i][3]);
        float4 c1 = make_float4(acc[i][4], acc[i][5], acc[i][6], acc[i][7]);
        *(float4*)(cp + tx * 4) = c0;
        *(float4*)(cp + 64 + tx * 4) = c1;
    }
}

// Q/K/V projections: gridDim.z selects the weight & output slab
__global__ void __launch_bounds__(256, 2)
qkv_gemm_kernel(const float* __restrict__ x,
                const float* __restrict__ Wq,
                const float* __restrict__ Wk,
                const float* __restrict__ Wv)
{
    const float* B = (blockIdx.z == 0) ? Wq : ((blockIdx.z == 1) ? Wk : Wv);
    float* C = g_QKV + (size_t)blockIdx.z * MDIM * NDIM;
    gemm_tn_128x128(x, B, C);
}

// Final projection: out = g_attn @ Wfc^T
__global__ void __launch_bounds__(256, 2)
fc_gemm_kernel(const float* __restrict__ Wfc, float* __restrict__ out)
{
    gemm_tn_128x128(g_attn, Wfc, out);
}

// ---------------------------------------------------------------------------
// Per-token attention over the heads axis.
// scores[h,t] = (1/8) * sum_d Q[tok,h,d]*K[tok,t,d]   (16x16)
// attn = softmax_t(scores); out[h,d] = sum_t attn[h,t]*V[tok,t,d]
// 16 threads per token (1 per head), 256 threads/block = 16 tokens/block.
// ---------------------------------------------------------------------------
__global__ void __launch_bounds__(256)
attn_kernel()
{
    const int token = blockIdx.x * 16 + (threadIdx.x >> 4);
    const int h = threadIdx.x & 15;

    const float4* Q4 = (const float4*)(g_QKV) + (size_t)token * 256 + h * 16;
    const float4* K4 = (const float4*)(g_QKV + (size_t)MDIM * NDIM) + (size_t)token * 256;
    const float4* V4 = (const float4*)(g_QKV + 2ull * MDIM * NDIM) + (size_t)token * 256;

    float4 q[16];
#pragma unroll
    for (int i = 0; i < 16; i++) q[i] = Q4[i];

    float s[16];
#pragma unroll
    for (int t = 0; t < 16; t++) {
        float acc = 0.0f;
#pragma unroll
        for (int dd = 0; dd < 16; dd++) {
            float4 kv = __ldg(&K4[t * 16 + dd]);
            acc = fmaf(q[dd].x, kv.x, acc);
            acc = fmaf(q[dd].y, kv.y, acc);
            acc = fmaf(q[dd].z, kv.z, acc);
            acc = fmaf(q[dd].w, kv.w, acc);
        }
        s[t] = acc * 0.125f;  // 1/sqrt(64)
    }

    float mx = s[0];
#pragma unroll
    for (int t = 1; t < 16; t++) mx = fmaxf(mx, s[t]);
    float sum = 0.0f;
#pragma unroll
    for (int t = 0; t < 16; t++) { s[t] = expf(s[t] - mx); sum += s[t]; }
    const float inv = 1.0f / sum;

    float4 o[16];
#pragma unroll
    for (int i = 0; i < 16; i++) o[i] = make_float4(0.f, 0.f, 0.f, 0.f);
#pragma unroll
    for (int t = 0; t < 16; t++) {
        const float p = s[t] * inv;
#pragma unroll
        for (int dd = 0; dd < 16; dd++) {
            float4 vv = __ldg(&V4[t * 16 + dd]);
            o[dd].x = fmaf(p, vv.x, o[dd].x);
            o[dd].y = fmaf(p, vv.y, o[dd].y);
            o[dd].z = fmaf(p, vv.z, o[dd].z);
            o[dd].w = fmaf(p, vv.w, o[dd].w);
        }
    }

    float4* O4 = (float4*)(g_attn) + (size_t)token * 256 + h * 16;
#pragma unroll
    for (int i = 0; i < 16; i++) O4[i] = o[i];
}

extern "C" void kernel_launch(void* const* d_in, const int* in_sizes, int n_in,
                              void* d_out, int out_size)
{
    const float* x   = (const float*)d_in[0];
    const float* Wq  = (const float*)d_in[1];
    const float* Wk  = (const float*)d_in[2];
    const float* Wv  = (const float*)d_in[3];
    const float* Wfc = (const float*)d_in[4];
    float* out = (float*)d_out;

    dim3 gQKV(NDIM / 128, MDIM / 128, 3);
    qkv_gemm_kernel<<<gQKV, 256>>>(x, Wq, Wk, Wv);

    attn_kernel<<<MDIM / 16, 256>>>();

    dim3 gFC(NDIM / 128, MDIM / 128, 1);
    fc_gemm_kernel<<<gFC, 256>>>(Wfc, out);
}

// round 3
// speedup vs baseline: 1.7034x; 1.7034x over previous
#include <cuda_runtime.h>
#include <cuda_bf16.h>
#include <math.h>
#include <stdint.h>

// Problem dims (fixed): B=4, S=4096, DM=1024, H=16, HD=64
#define MDIM 16384   // B*S tokens
#define NDIM 1024
#define KDIM 1024

// ---------------------------------------------------------------------------
// Device scratch (no allocations allowed in kernel_launch)
// ---------------------------------------------------------------------------
__device__ __nv_bfloat16 g_xhi[(size_t)MDIM * KDIM];
__device__ __nv_bfloat16 g_xlo[(size_t)MDIM * KDIM];
__device__ __nv_bfloat16 g_whi[4ull * NDIM * KDIM];   // [Wq|Wk|Wv|Wfc]
__device__ __nv_bfloat16 g_wlo[4ull * NDIM * KDIM];
__device__ float         g_QKV[3ull * MDIM * NDIM];   // fp32 Q|K|V
__device__ __nv_bfloat16 g_ahi[(size_t)MDIM * NDIM];  // attn out hi
__device__ __nv_bfloat16 g_alo[(size_t)MDIM * NDIM];  // attn out lo

// ---------------------------------------------------------------------------
// Generic-PTX tensor core helpers (legal on plain sm_103 target)
// ---------------------------------------------------------------------------
__device__ __forceinline__ uint32_t smem_to_u32(const void* p) {
    uint32_t a;
    asm("{ .reg .u64 t; cvta.to.shared.u64 t, %1; cvt.u32.u64 %0, t; }" : "=r"(a) : "l"(p));
    return a;
}

__device__ __forceinline__ void cp_async16(uint32_t dst, const void* src) {
    asm volatile("cp.async.cg.shared.global [%0], [%1], 16;" :: "r"(dst), "l"(src) : "memory");
}
#define CP_COMMIT() asm volatile("cp.async.commit_group;" ::: "memory")
#define CP_WAIT(n)  asm volatile("cp.async.wait_group %0;" :: "n"(n) : "memory")

#define LDSM_X4(r0, r1, r2, r3, addr) \
    asm volatile("ldmatrix.sync.aligned.m8n8.x4.shared.b16 {%0,%1,%2,%3}, [%4];" \
                 : "=r"(r0), "=r"(r1), "=r"(r2), "=r"(r3) : "r"(addr))

#define MMA16816(d, a, b0, b1) \
    asm volatile("mma.sync.aligned.m16n8k16.row.col.f32.bf16.bf16.f32 " \
                 "{%0,%1,%2,%3},{%4,%5,%6,%7},{%8,%9},{%0,%1,%2,%3};" \
                 : "+f"((d)[0]), "+f"((d)[1]), "+f"((d)[2]), "+f"((d)[3]) \
                 : "r"((a)[0]), "r"((a)[1]), "r"((a)[2]), "r"((a)[3]), \
                   "r"(b0), "r"(b1))

// ---------------------------------------------------------------------------
// bf16x3 GEMM: C[m,n] = sum_k A[m,k] * B[n,k]   (both K-contiguous)
// 128x128x32 tile, 256 threads, 8 warps (4m x 2n), warp tile 32m x 64n.
// SMEM per stage: 4 tiles (Ah, Al, Bh, Bl) of 128x32 bf16, rows padded to 40.
// ---------------------------------------------------------------------------
#define ROWB 80                                   // padded row bytes (40 bf16)
#define TILE_BYTES (128 * ROWB)                   // 10240
#define STAGE_BYTES (4 * TILE_BYTES)              // 40960
#define SMEM_DYN_BYTES (2 * STAGE_BYTES)          // 81920
#define OFF_AH 0
#define OFF_AL TILE_BYTES
#define OFF_BH (2 * TILE_BYTES)
#define OFF_BL (3 * TILE_BYTES)
#define NCHUNK (KDIM / 32)                        // 32

__device__ __forceinline__ void stage_load(
    uint32_t sb, const __nv_bfloat16* Ahp, const __nv_bfloat16* Alp,
    const __nv_bfloat16* Bhp, const __nv_bfloat16* Blp, int k0)
{
    const int tid = threadIdx.x;
    const int row = tid >> 1;
    const int half = tid & 1;                     // 0 or 1 -> 32B each
    const uint32_t soff = (uint32_t)row * ROWB + half * 32;
    const size_t goff = (size_t)row * KDIM + half * 16 + k0;
    cp_async16(sb + OFF_AH + soff,      Ahp + goff);
    cp_async16(sb + OFF_AH + soff + 16, Ahp + goff + 8);
    cp_async16(sb + OFF_AL + soff,      Alp + goff);
    cp_async16(sb + OFF_AL + soff + 16, Alp + goff + 8);
    cp_async16(sb + OFF_BH + soff,      Bhp + goff);
    cp_async16(sb + OFF_BH + soff + 16, Bhp + goff + 8);
    cp_async16(sb + OFF_BL + soff,      Blp + goff);
    cp_async16(sb + OFF_BL + soff + 16, Blp + goff + 8);
    CP_COMMIT();
}

__device__ void gemm_bf16x3(const __nv_bfloat16* __restrict__ Ahi,
                            const __nv_bfloat16* __restrict__ Alo,
                            const __nv_bfloat16* __restrict__ Bhi,
                            const __nv_bfloat16* __restrict__ Blo,
                            float* __restrict__ C)
{
    extern __shared__ char smem_raw[];
    const uint32_t base = smem_to_u32(smem_raw);

    const int tid = threadIdx.x;
    const int wid = tid >> 5;
    const int lane = tid & 31;
    const int warp_m = (wid & 3) * 32;            // 0,32,64,96
    const int warp_n = (wid >> 2) * 64;           // 0,64
    const int mBase = blockIdx.y * 128;
    const int nBase = blockIdx.x * 128;

    const __nv_bfloat16* Ahp = Ahi + (size_t)mBase * KDIM;
    const __nv_bfloat16* Alp = Alo + (size_t)mBase * KDIM;
    const __nv_bfloat16* Bhp = Bhi + (size_t)nBase * KDIM;
    const __nv_bfloat16* Blp = Blo + (size_t)nBase * KDIM;

    // ldmatrix per-lane relative offsets (within a tile), k-half via (lane>>4)
    uint32_t a_off[2], b_off[4];
#pragma unroll
    for (int i = 0; i < 2; i++)
        a_off[i] = (uint32_t)(warp_m + i * 16 + (lane & 15)) * ROWB + ((lane >> 4) << 4);
#pragma unroll
    for (int jj = 0; jj < 4; jj++)
        b_off[jj] = (uint32_t)(warp_n + jj * 16 + (lane & 15)) * ROWB + ((lane >> 4) << 4);

    float acc[2][8][4];
#pragma unroll
    for (int i = 0; i < 2; i++)
#pragma unroll
        for (int j = 0; j < 8; j++)
#pragma unroll
            for (int q = 0; q < 4; q++) acc[i][j][q] = 0.0f;

    stage_load(base,               Ahp, Alp, Bhp, Blp, 0);
    stage_load(base + STAGE_BYTES, Ahp, Alp, Bhp, Blp, 32);

#pragma unroll 1
    for (int c = 0; c < NCHUNK; c++) {
        if (c < NCHUNK - 1) { CP_WAIT(1); } else { CP_WAIT(0); }
        __syncthreads();

        const uint32_t sb = base + (c & 1) * STAGE_BYTES;

#pragma unroll
        for (int kk = 0; kk < 2; kk++) {
            const uint32_t ko = kk * 32;          // 16 bf16 = 32 bytes
            uint32_t ah[2][4], al[2][4];
#pragma unroll
            for (int i = 0; i < 2; i++) {
                LDSM_X4(ah[i][0], ah[i][1], ah[i][2], ah[i][3], sb + OFF_AH + a_off[i] + ko);
                LDSM_X4(al[i][0], al[i][1], al[i][2], al[i][3], sb + OFF_AL + a_off[i] + ko);
            }
            uint32_t bh[4][4], bl[4][4];
#pragma unroll
            for (int jj = 0; jj < 4; jj++) {
                LDSM_X4(bh[jj][0], bh[jj][1], bh[jj][2], bh[jj][3], sb + OFF_BH + b_off[jj] + ko);
                LDSM_X4(bl[jj][0], bl[jj][1], bl[jj][2], bl[jj][3], sb + OFF_BL + b_off[jj] + ko);
            }
#pragma unroll
            for (int i = 0; i < 2; i++) {
#pragma unroll
                for (int jj = 0; jj < 4; jj++) {
                    // even n-frag (regs 0,2), odd n-frag (regs 1,3)
                    MMA16816(acc[i][2 * jj],     ah[i], bh[jj][0], bh[jj][2]);
                    MMA16816(acc[i][2 * jj],     ah[i], bl[jj][0], bl[jj][2]);
                    MMA16816(acc[i][2 * jj],     al[i], bh[jj][0], bh[jj][2]);
                    MMA16816(acc[i][2 * jj + 1], ah[i], bh[jj][1], bh[jj][3]);
                    MMA16816(acc[i][2 * jj + 1], ah[i], bl[jj][1], bl[jj][3]);
                    MMA16816(acc[i][2 * jj + 1], al[i], bh[jj][1], bh[jj][3]);
                }
            }
        }

        __syncthreads();
        if (c + 2 < NCHUNK)
            stage_load(base + (c & 1) * STAGE_BYTES, Ahp, Alp, Bhp, Blp, (c + 2) * 32);
    }

    // epilogue: fp32 store
#pragma unroll
    for (int i = 0; i < 2; i++) {
        const int r0 = mBase + warp_m + i * 16 + (lane >> 2);
#pragma unroll
        for (int j = 0; j < 8; j++) {
            const int col = nBase + warp_n + j * 8 + (lane & 3) * 2;
            *(float2*)(C + (size_t)r0 * NDIM + col) =
                make_float2(acc[i][j][0], acc[i][j][1]);
            *(float2*)(C + (size_t)(r0 + 8) * NDIM + col) =
                make_float2(acc[i][j][2], acc[i][j][3]);
        }
    }
}

__global__ void __launch_bounds__(256, 1)
qkv_mm_kernel()
{
    const int z = blockIdx.z;
    gemm_bf16x3(g_xhi, g_xlo,
                g_whi + (size_t)z * NDIM * KDIM,
                g_wlo + (size_t)z * NDIM * KDIM,
                g_QKV + (size_t)z * MDIM * NDIM);
}

__global__ void __launch_bounds__(256, 1)
fc_mm_kernel(float* __restrict__ out)
{
    gemm_bf16x3(g_ahi, g_alo,
                g_whi + 3ull * NDIM * KDIM,
                g_wlo + 3ull * NDIM * KDIM,
                out);
}

// ---------------------------------------------------------------------------
// fp32 -> bf16 hi/lo split
// ---------------------------------------------------------------------------
__device__ __forceinline__ void split1(float a, __nv_bfloat16& h, __nv_bfloat16& l) {
    h = __float2bfloat16(a);
    l = __float2bfloat16(a - __bfloat162float(h));
}

__global__ void __launch_bounds__(256)
split_kernel(const float* __restrict__ src, __nv_bfloat16* __restrict__ hi,
             __nv_bfloat16* __restrict__ lo, int n4)
{
    const int i = blockIdx.x * blockDim.x + threadIdx.x;
    if (i >= n4) return;
    float4 v = ((const float4*)src)[i];
    __nv_bfloat16 hx, hy, hz, hw, lx, ly, lz, lw;
    split1(v.x, hx, lx); split1(v.y, hy, ly);
    split1(v.z, hz, lz); split1(v.w, hw, lw);
    __nv_bfloat162* H = (__nv_bfloat162*)hi;
    __nv_bfloat162* L = (__nv_bfloat162*)lo;
    H[2 * i]     = __nv_bfloat162(hx, hy);
    H[2 * i + 1] = __nv_bfloat162(hz, hw);
    L[2 * i]     = __nv_bfloat162(lx, ly);
    L[2 * i + 1] = __nv_bfloat162(lz, lw);
}

// ---------------------------------------------------------------------------
// Per-token attention over the heads axis (16x16 per token), fp32 in,
// writes hi/lo bf16 for the fc GEMM.
// ---------------------------------------------------------------------------
__global__ void __launch_bounds__(256)
attn_kernel()
{
    const int token = blockIdx.x * 16 + (threadIdx.x >> 4);
    const int h = threadIdx.x & 15;

    const float4* Q4 = (const float4*)(g_QKV) + (size_t)token * 256 + h * 16;
    const float4* K4 = (const float4*)(g_QKV + (size_t)MDIM * NDIM) + (size_t)token * 256;
    const float4* V4 = (const float4*)(g_QKV + 2ull * MDIM * NDIM) + (size_t)token * 256;

    float4 q[16];
#pragma unroll
    for (int i = 0; i < 16; i++) q[i] = Q4[i];

    float s[16];
#pragma unroll
    for (int t = 0; t < 16; t++) {
        float acc = 0.0f;
#pragma unroll
        for (int dd = 0; dd < 16; dd++) {
            float4 kv = __ldg(&K4[t * 16 + dd]);
            acc = fmaf(q[dd].x, kv.x, acc);
            acc = fmaf(q[dd].y, kv.y, acc);
            acc = fmaf(q[dd].z, kv.z, acc);
            acc = fmaf(q[dd].w, kv.w, acc);
        }
        s[t] = acc * 0.125f;
    }

    float mx = s[0];
#pragma unroll
    for (int t = 1; t < 16; t++) mx = fmaxf(mx, s[t]);
    float sum = 0.0f;
#pragma unroll
    for (int t = 0; t < 16; t++) { s[t] = expf(s[t] - mx); sum += s[t]; }
    const float inv = 1.0f / sum;

    float4 o[16];
#pragma unroll
    for (int i = 0; i < 16; i++) o[i] = make_float4(0.f, 0.f, 0.f, 0.f);
#pragma unroll
    for (int t = 0; t < 16; t++) {
        const float p = s[t] * inv;
#pragma unroll
        for (int dd = 0; dd < 16; dd++) {
            float4 vv = __ldg(&V4[t * 16 + dd]);
            o[dd].x = fmaf(p, vv.x, o[dd].x);
            o[dd].y = fmaf(p, vv.y, o[dd].y);
            o[dd].z = fmaf(p, vv.z, o[dd].z);
            o[dd].w = fmaf(p, vv.w, o[dd].w);
        }
    }

    const size_t obase = (size_t)token * NDIM + h * 64;
    __nv_bfloat162* OH = (__nv_bfloat162*)(g_ahi + obase);
    __nv_bfloat162* OL = (__nv_bfloat162*)(g_alo + obase);
#pragma unroll
    for (int i = 0; i < 16; i++) {
        __nv_bfloat16 hx, hy, hz, hw, lx, ly, lz, lw;
        split1(o[i].x, hx, lx); split1(o[i].y, hy, ly);
        split1(o[i].z, hz, lz); split1(o[i].w, hw, lw);
        OH[2 * i]     = __nv_bfloat162(hx, hy);
        OH[2 * i + 1] = __nv_bfloat162(hz, hw);
        OL[2 * i]     = __nv_bfloat162(lx, ly);
        OL[2 * i + 1] = __nv_bfloat162(lz, lw);
    }
}

// ---------------------------------------------------------------------------
extern "C" void kernel_launch(void* const* d_in, const int* in_sizes, int n_in,
                              void* d_out, int out_size)
{
    const float* x   = (const float*)d_in[0];
    const float* Wq  = (const float*)d_in[1];
    const float* Wk  = (const float*)d_in[2];
    const float* Wv  = (const float*)d_in[3];
    const float* Wfc = (const float*)d_in[4];
    float* out = (float*)d_out;

    cudaFuncSetAttribute(qkv_mm_kernel, cudaFuncAttributeMaxDynamicSharedMemorySize, SMEM_DYN_BYTES);
    cudaFuncSetAttribute(fc_mm_kernel,  cudaFuncAttributeMaxDynamicSharedMemorySize, SMEM_DYN_BYTES);

    __nv_bfloat16 *xhi_p, *xlo_p, *whi_p, *wlo_p;
    cudaGetSymbolAddress((void**)&xhi_p, g_xhi);
    cudaGetSymbolAddress((void**)&xlo_p, g_xlo);
    cudaGetSymbolAddress((void**)&whi_p, g_whi);
    cudaGetSymbolAddress((void**)&wlo_p, g_wlo);

    {
        int n4 = (MDIM * KDIM) / 4;
        split_kernel<<<(n4 + 255) / 256, 256>>>(x, xhi_p, xlo_p, n4);
        int w4 = (NDIM * KDIM) / 4;
        split_kernel<<<(w4 + 255) / 256, 256>>>(Wq,  whi_p + 0ull * NDIM * KDIM, wlo_p + 0ull * NDIM * KDIM, w4);
        split_kernel<<<(w4 + 255) / 256, 256>>>(Wk,  whi_p + 1ull * NDIM * KDIM, wlo_p + 1ull * NDIM * KDIM, w4);
        split_kernel<<<(w4 + 255) / 256, 256>>>(Wv,  whi_p + 2ull * NDIM * KDIM, wlo_p + 2ull * NDIM * KDIM, w4);
        split_kernel<<<(w4 + 255) / 256, 256>>>(Wfc, whi_p + 3ull * NDIM * KDIM, wlo_p + 3ull * NDIM * KDIM, w4);
    }

    dim3 gQKV(NDIM / 128, MDIM / 128, 3);
    qkv_mm_kernel<<<gQKV, 256, SMEM_DYN_BYTES>>>();

    attn_kernel<<<MDIM / 16, 256>>>();

    dim3 gFC(NDIM / 128, MDIM / 128, 1);
    fc_mm_kernel<<<gFC, 256, SMEM_DYN_BYTES>>>(out);
}